// round 8
// baseline (speedup 1.0000x reference)
#include <cuda_runtime.h>
#include <cuda_bf16.h>
#include <float.h>

#define BB     64
#define SS     2048
#define HH     2048
#define HQ     16
#define HKV    4
#define DD     128
#define RDIM   64
#define GG     4
#define CQKV   3072          // HQ*D + 2*HKV*D
#define SKN    16            // split-K factor
#define KCH    (HH / SKN)    // 128
#define CHUNK  256
#define NSPLIT (SS / CHUNK)  // 8
#define NT     64            // tokens staged per smem tile in attention
#define EPSV   1e-6f
#define SCALEV 0.08838834764831843f  // 128^-0.5

// ---------------- scratch (device globals; no allocs allowed) ---------------
__device__ float g_qkv_part[SKN * BB * CQKV];          // 12.6 MB
__device__ float g_qbuf[BB * HQ * DD];                 // q, pre-scaled
__device__ float g_knew[BB * HKV * DD];
__device__ float g_vnew[BB * HKV * DD];
__device__ float g_po[BB * HKV * NSPLIT * GG * DD];    // 4 MB partial O
__device__ float g_pm[BB * HKV * NSPLIT * GG];
__device__ float g_pl[BB * HKV * NSPLIT * GG];
__device__ float g_attn[BB * HQ * DD];
__device__ float g_wo_part[SKN * BB * HH];             // 8.4 MB

// ---------------- skinny split-K SGEMM: out[b][c] = sum_k X[b][k]*W[c][k] ---
// Tile: 64 rows (all of B) x 128 cols, Kc=32 per stage, 256 threads,
// 4x8 microtile, register-staged global prefetch (6 x LDG.128 per stage).
template <int SEL>
__global__ void __launch_bounds__(256)
sgemm_part(const float* __restrict__ Xin,
           const float* __restrict__ W1,
           const float* __restrict__ W2,
           const float* __restrict__ W3,
           int c1, int c2, int C)
{
    const float* X    = (SEL == 0) ? Xin : g_attn;
    float*       outp = (SEL == 0) ? g_qkv_part : g_wo_part;

    int n0 = blockIdx.x * 128;
    int sk = blockIdx.y;
    const float* W; int woff;
    if (n0 < c1)      { W = W1; woff = 0;  }
    else if (n0 < c2) { W = W2; woff = c1; }
    else              { W = W3; woff = c2; }
    const float* Wb = W + (size_t)(n0 - woff) * HH;

    __shared__ __align__(16) float As[32][64];    // 8 KB
    __shared__ __align__(16) float Bs[32][128];   // 16 KB

    int tid = threadIdx.x;
    int ty  = tid >> 4;          // 0..15 -> rows ty*4..ty*4+3
    int tx  = tid & 15;          // 0..15 -> cols tx*8..tx*8+7

    int kbase = sk * KCH;
    const float* Ab = X  + kbase;
    const float* Bb = Wb + kbase;

    float4 pa[2], pb[4];
#pragma unroll
    for (int j = 0; j < 2; j++) {
        int idx = tid + j * 256;
        pa[j] = *(const float4*)(Ab + (size_t)(idx >> 3) * HH + ((idx & 7) << 2));
    }
#pragma unroll
    for (int j = 0; j < 4; j++) {
        int idx = tid + j * 256;
        pb[j] = *(const float4*)(Bb + (size_t)(idx >> 3) * HH + ((idx & 7) << 2));
    }

    float acc[4][8] = {};

    for (int kt = 0; kt < KCH; kt += 32) {
#pragma unroll
        for (int j = 0; j < 2; j++) {
            int idx = tid + j * 256, rr = idx >> 3, oo = (idx & 7) << 2;
            As[oo + 0][rr] = pa[j].x; As[oo + 1][rr] = pa[j].y;
            As[oo + 2][rr] = pa[j].z; As[oo + 3][rr] = pa[j].w;
        }
#pragma unroll
        for (int j = 0; j < 4; j++) {
            int idx = tid + j * 256, rr = idx >> 3, oo = (idx & 7) << 2;
            Bs[oo + 0][rr] = pb[j].x; Bs[oo + 1][rr] = pb[j].y;
            Bs[oo + 2][rr] = pb[j].z; Bs[oo + 3][rr] = pb[j].w;
        }
        __syncthreads();

        if (kt + 32 < KCH) {                 // prefetch next stage during compute
#pragma unroll
            for (int j = 0; j < 2; j++) {
                int idx = tid + j * 256;
                pa[j] = *(const float4*)(Ab + (size_t)(idx >> 3) * HH + kt + 32 + ((idx & 7) << 2));
            }
#pragma unroll
            for (int j = 0; j < 4; j++) {
                int idx = tid + j * 256;
                pb[j] = *(const float4*)(Bb + (size_t)(idx >> 3) * HH + kt + 32 + ((idx & 7) << 2));
            }
        }

#pragma unroll
        for (int k = 0; k < 32; k++) {
            float4 a  = *(const float4*)&As[k][ty * 4];
            float4 bA = *(const float4*)&Bs[k][tx * 8];
            float4 bB = *(const float4*)&Bs[k][tx * 8 + 4];
            float av[4] = {a.x, a.y, a.z, a.w};
#pragma unroll
            for (int i = 0; i < 4; i++) {
                acc[i][0] = fmaf(av[i], bA.x, acc[i][0]);
                acc[i][1] = fmaf(av[i], bA.y, acc[i][1]);
                acc[i][2] = fmaf(av[i], bA.z, acc[i][2]);
                acc[i][3] = fmaf(av[i], bA.w, acc[i][3]);
                acc[i][4] = fmaf(av[i], bB.x, acc[i][4]);
                acc[i][5] = fmaf(av[i], bB.y, acc[i][5]);
                acc[i][6] = fmaf(av[i], bB.z, acc[i][6]);
                acc[i][7] = fmaf(av[i], bB.w, acc[i][7]);
            }
        }
        __syncthreads();
    }

    float* op = outp + (size_t)sk * BB * C;
#pragma unroll
    for (int i = 0; i < 4; i++) {
        *(float4*)&op[(size_t)(ty * 4 + i) * C + n0 + tx * 8] =
            make_float4(acc[i][0], acc[i][1], acc[i][2], acc[i][3]);
        *(float4*)&op[(size_t)(ty * 4 + i) * C + n0 + tx * 8 + 4] =
            make_float4(acc[i][4], acc[i][5], acc[i][6], acc[i][7]);
    }
}

// ---------------- split-K reduce + RMSNorm + RoPE + staging ------------------
__global__ void __launch_bounds__(128)
rms_rope_kernel(const float* __restrict__ qw, const float* __restrict__ kw,
                const float* __restrict__ cosp, const float* __restrict__ sinp)
{
    int b  = blockIdx.x;
    int hh = blockIdx.y;   // 0..23: [0,16) q, [16,20) k, [20,24) v
    int d  = threadIdx.x;  // 0..127

    int col, kind;
    if (hh < HQ)            { kind = 0; col = hh * DD + d; }
    else if (hh < HQ + HKV) { kind = 1; col = HH + (hh - HQ) * DD + d; }
    else                    { kind = 2; col = HH + HKV * DD + (hh - HQ - HKV) * DD + d; }

    float val = 0.f;
#pragma unroll
    for (int s = 0; s < SKN; s++)
        val += g_qkv_part[(size_t)s * BB * CQKV + (size_t)b * CQKV + col];

    if (kind == 2) {  // v: no norm, no rope
        g_vnew[(b * HKV + (hh - HQ - HKV)) * DD + d] = val;
        return;
    }

    __shared__ float red[4];
    __shared__ float xs[DD];

    float sq = val * val;
#pragma unroll
    for (int o = 16; o > 0; o >>= 1) sq += __shfl_xor_sync(0xffffffffu, sq, o);
    if ((d & 31) == 0) red[d >> 5] = sq;
    __syncthreads();
    float var = (red[0] + red[1] + red[2] + red[3]) * (1.f / DD);
    float r   = rsqrtf(var + EPSV);

    const float* w = (kind == 0) ? qw : kw;
    val = w[d] * val * r;
    xs[d] = val;
    __syncthreads();

    float outv = val;
    if (d < RDIM) {
        float c  = cosp[b * RDIM + d];
        float s2 = sinp[b * RDIM + d];
        float other = (d < RDIM / 2) ? -xs[d + RDIM / 2] : xs[d - RDIM / 2];
        outv = val * c + other * s2;
    }
    if (kind == 0) g_qbuf[(b * HQ + hh) * DD + d] = outv * SCALEV;  // fold score scale
    else           g_knew[(b * HKV + (hh - HQ)) * DD + d] = outv;
}

// ---------------- flash-decode partial attention ----------------------------
// K/V staged through smem in 64-token tiles: each thread issues 8 independent
// LDG.128s per tile (high MLP), then compute reads smem.
__global__ void __launch_bounds__(256)
attn_partial(const float* __restrict__ kc, const float* __restrict__ vc,
             const int* __restrict__ r2t, const int* __restrict__ rpi,
             const int* __restrict__ slen, const int* __restrict__ loc)
{
    int b  = blockIdx.x;
    int kv = blockIdx.y;
    int sp = blockIdx.z;
    int L  = slen[b];
    int start = sp * CHUNK;
    if (start >= L) return;
    int end = min(start + CHUNK, L);
    int n   = end - start;

    int tid  = threadIdx.x;
    int w    = tid >> 5;
    int lane = tid & 31;
    int myloc = loc[b];
    int rbase = rpi[b] * SS;

    __shared__ __align__(16) float qs[GG][DD];   // 2 KB
    __shared__ __align__(16) float kt[NT][DD];   // 32 KB staged K/V tile
    __shared__ float sc[GG][CHUNK];              // 4 KB (scores -> probs)
    __shared__ float buf[2][GG][DD];             // 4 KB (PV parity reduce)
    __shared__ int   tok_s[CHUNK];               // 1 KB
    __shared__ float red[8];

    for (int i = tid; i < GG * DD; i += 256)
        qs[i >> 7][i & 127] = g_qbuf[(b * HQ + kv * GG + (i >> 7)) * DD + (i & 127)];
    for (int t = tid; t < n; t += 256)
        tok_s[t] = r2t[rbase + start + t];
    __syncthreads();

    // Hoist q into registers (constant across all tiles).
    float4 q0 = *((const float4*)&qs[0][0] + lane);
    float4 q1 = *((const float4*)&qs[1][0] + lane);
    float4 q2 = *((const float4*)&qs[2][0] + lane);
    float4 q3 = *((const float4*)&qs[3][0] + lane);

    // Phase 1: scores via smem-staged K tiles.
    const float* knewp = g_knew + (b * HKV + kv) * DD;
    for (int tt = 0; tt < n; tt += NT) {
        int nt = min(NT, n - tt);
        __syncthreads();   // previous tile fully consumed
#pragma unroll
        for (int j = 0; j < 8; j++) {
            int t = w + j * 8;                       // warp-uniform token row
            float4 val = make_float4(0.f, 0.f, 0.f, 0.f);
            if (t < nt) {
                int tk = tok_s[tt + t];
                const float* kp = (tk == myloc) ? knewp
                                                : (kc + ((size_t)tk * HKV + kv) * DD);
                val = *((const float4*)kp + lane);
            }
            *((float4*)&kt[t][0] + lane) = val;
        }
        __syncthreads();
        for (int t0 = w; t0 < nt; t0 += 8) {
            float4 k4 = *((const float4*)&kt[t0][0] + lane);
            float s0 = k4.x * q0.x + k4.y * q0.y + k4.z * q0.z + k4.w * q0.w;
            float s1 = k4.x * q1.x + k4.y * q1.y + k4.z * q1.z + k4.w * q1.w;
            float s2 = k4.x * q2.x + k4.y * q2.y + k4.z * q2.z + k4.w * q2.w;
            float s3 = k4.x * q3.x + k4.y * q3.y + k4.z * q3.z + k4.w * q3.w;
#pragma unroll
            for (int o = 16; o > 0; o >>= 1) {
                s0 += __shfl_xor_sync(0xffffffffu, s0, o);
                s1 += __shfl_xor_sync(0xffffffffu, s1, o);
                s2 += __shfl_xor_sync(0xffffffffu, s2, o);
                s3 += __shfl_xor_sync(0xffffffffu, s3, o);
            }
            if (lane == 0) {
                sc[0][tt + t0] = s0; sc[1][tt + t0] = s1;
                sc[2][tt + t0] = s2; sc[3][tt + t0] = s3;
            }
        }
    }
    __syncthreads();

    // Phase 2: per-g chunk max, exp, sum; store (m, l).
    int mlbase = ((b * HKV + kv) * NSPLIT + sp) * GG;
#pragma unroll
    for (int g = 0; g < GG; g++) {
        float v  = (tid < n) ? sc[g][tid] : -FLT_MAX;
        float mv = v;
#pragma unroll
        for (int o = 16; o > 0; o >>= 1)
            mv = fmaxf(mv, __shfl_xor_sync(0xffffffffu, mv, o));
        if (lane == 0) red[w] = mv;
        __syncthreads();
        float mg = red[0];
#pragma unroll
        for (int i = 1; i < 8; i++) mg = fmaxf(mg, red[i]);
        float e = (tid < n) ? __expf(v - mg) : 0.f;
        if (tid < n) sc[g][tid] = e;
        float sv = e;
#pragma unroll
        for (int o = 16; o > 0; o >>= 1)
            sv += __shfl_xor_sync(0xffffffffu, sv, o);
        __syncthreads();                 // all mg reads done before overwrite
        if (lane == 0) red[w] = sv;
        __syncthreads();
        if (tid == 0) {
            float lg = 0.f;
#pragma unroll
            for (int i = 0; i < 8; i++) lg += red[i];
            g_pm[mlbase + g] = mg;
            g_pl[mlbase + g] = lg;
        }
        __syncthreads();                 // protect red for next g
    }

    // Phase 3: PV via smem-staged V tiles. 2 token parities x 128 d-threads;
    // each thread accumulates all 4 head-groups.
    int tp = tid >> 7;
    int d  = tid & 127;
    float a0 = 0.f, a1 = 0.f, a2 = 0.f, a3 = 0.f;
    const float* vnewp = g_vnew + (b * HKV + kv) * DD;
    for (int tt = 0; tt < n; tt += NT) {
        int nt = min(NT, n - tt);
        __syncthreads();
#pragma unroll
        for (int j = 0; j < 8; j++) {
            int t = w + j * 8;
            float4 val = make_float4(0.f, 0.f, 0.f, 0.f);
            if (t < nt) {
                int tk = tok_s[tt + t];
                const float* vp = (tk == myloc) ? vnewp
                                                : (vc + ((size_t)tk * HKV + kv) * DD);
                val = *((const float4*)vp + lane);
            }
            *((float4*)&kt[t][0] + lane) = val;
        }
        __syncthreads();
#pragma unroll 4
        for (int t = tp; t < nt; t += 2) {
            float vv = kt[t][d];
            a0 = fmaf(sc[0][tt + t], vv, a0);
            a1 = fmaf(sc[1][tt + t], vv, a1);
            a2 = fmaf(sc[2][tt + t], vv, a2);
            a3 = fmaf(sc[3][tt + t], vv, a3);
        }
    }
    buf[tp][0][d] = a0; buf[tp][1][d] = a1;
    buf[tp][2][d] = a2; buf[tp][3][d] = a3;
    __syncthreads();

    if (tid < DD) {
        int ob = ((b * HKV + kv) * NSPLIT + sp) * GG * DD;
#pragma unroll
        for (int g = 0; g < GG; g++)
            g_po[ob + g * DD + tid] = buf[0][g][tid] + buf[1][g][tid];
    }
}

// ---------------- combine splits (logsumexp) --------------------------------
__global__ void __launch_bounds__(128)
combine_kernel(const int* __restrict__ slen)
{
    int b = blockIdx.x;
    int h = blockIdx.y;            // 0..15 global q head
    int kv = h >> 2, g = h & 3;
    int d  = threadIdx.x;
    int L  = slen[b];
    int ns = (L + CHUNK - 1) / CHUNK;

    int mlbase = ((b * HKV + kv) * NSPLIT) * GG + g;
    float M = -FLT_MAX;
    for (int i = 0; i < ns; i++) M = fmaxf(M, g_pm[mlbase + i * GG]);

    float denom = 0.f, acc = 0.f;
    int obase = ((b * HKV + kv) * NSPLIT) * GG * DD + g * DD + d;
    for (int i = 0; i < ns; i++) {
        float wgt = __expf(g_pm[mlbase + i * GG] - M);
        denom += wgt * g_pl[mlbase + i * GG];
        acc   += wgt * g_po[obase + i * GG * DD];
    }
    g_attn[(b * HQ + h) * DD + d] = acc / denom;
}

// ---------------- Wo split-K reduce -> final output -------------------------
__global__ void __launch_bounds__(256)
wo_reduce(float* __restrict__ out)
{
    int i = blockIdx.x * 256 + threadIdx.x;   // 0..131071
    float s = 0.f;
#pragma unroll
    for (int k = 0; k < SKN; k++)
        s += g_wo_part[(size_t)k * BB * HH + i];
    out[i] = s;
}

// ---------------- launch -----------------------------------------------------
extern "C" void kernel_launch(void* const* d_in, const int* in_sizes, int n_in,
                              void* d_out, int out_size)
{
    const float* hid  = (const float*)d_in[0];
    const float* Wq   = (const float*)d_in[1];
    const float* Wk   = (const float*)d_in[2];
    const float* Wv   = (const float*)d_in[3];
    const float* qw   = (const float*)d_in[4];
    const float* kw   = (const float*)d_in[5];
    const float* Wo   = (const float*)d_in[6];
    const float* kc   = (const float*)d_in[7];
    const float* vc   = (const float*)d_in[8];
    const float* cosp = (const float*)d_in[9];
    const float* sinp = (const float*)d_in[10];
    const int*   r2t  = (const int*)d_in[11];
    const int*   rpi  = (const int*)d_in[12];
    const int*   slen = (const int*)d_in[13];
    const int*   loc  = (const int*)d_in[14];
    float* out = (float*)d_out;

    sgemm_part<0><<<dim3(CQKV / 128, SKN), 256>>>(hid, Wq, Wk, Wv, HH, HH + HKV * DD, CQKV);
    rms_rope_kernel<<<dim3(BB, HQ + 2 * HKV), 128>>>(qw, kw, cosp, sinp);
    attn_partial<<<dim3(BB, HKV, NSPLIT), 256>>>(kc, vc, r2t, rpi, slen, loc);
    combine_kernel<<<dim3(BB, HQ), 128>>>(slen);
    sgemm_part<1><<<dim3(HH / 128, SKN), 256>>>(nullptr, Wo, Wo, Wo, 2 * HH, 2 * HH, HH);
    wo_reduce<<<BB * HH / 256, 256>>>(out);
}